// round 8
// baseline (speedup 1.0000x reference)
#include <cuda_runtime.h>
#include <cuda_bf16.h>
#include <math.h>
#include <stdint.h>

// Problem constants
#define B_ 2
#define T_ 2048
#define C_ 1024
#define H_ 16
#define D_ 64
#define WIN_ 512
#define K_ 1024

// int8 GEMM tiling: K=32 bytes per stage tile row, 4-stage cp.async
#define ISP 48                       // padded row stride (bytes): conflict-free, 16B-aligned
#define ITILE_B (128 * ISP)          // 6144 B per 128xK32 tile
#define ISTAGE_B (4 * ITILE_B)       // A1, A0, B1, B0 = 24576 B
#define INSTAGE 4
#define IGSMEM (INSTAGE * ISTAGE_B)  // 98304 B

// Attention smem
#define ASP 72                       // padded row stride (bf16 elems)
#define ATTN_SMEM ((2*128 + 4*64) * ASP * 2)   // 73728 bytes

// ---------------- scratch (allocation-free) ----------------
__device__ __nv_bfloat16 g_Qh[B_*H_*T_*D_], g_Ql[B_*H_*T_*D_];
__device__ __nv_bfloat16 g_Kh[B_*H_*T_*D_], g_Kl[B_*H_*T_*D_];
__device__ __nv_bfloat16 g_Vh[B_*H_*T_*D_], g_Vl[B_*H_*T_*D_];
__device__ int8_t g_xq1[B_*T_*C_], g_xq0[B_*T_*C_];
__device__ int8_t g_wq1[3*C_*C_],  g_wq0[3*C_*C_];
__device__ int8_t g_wp1[C_*C_],    g_wp0[C_*C_];
__device__ int8_t g_yq1[B_*T_*C_], g_yq0[B_*T_*C_];
__device__ float  g_sx[B_*T_], g_swq[3*C_], g_swp[C_], g_sy[B_*T_];
__device__ float  g_y[B_*T_*C_];

__device__ __forceinline__ uint32_t smem_u32(const void* p) {
    uint32_t a;
    asm("{ .reg .u64 t; cvta.to.shared.u64 t, %1; cvt.u32.u64 %0, t; }"
        : "=r"(a) : "l"(p));
    return a;
}
#define LDMX4(r0, r1, r2, r3, addr)                                          \
    asm volatile("ldmatrix.sync.aligned.m8n8.x4.shared.b16 {%0,%1,%2,%3}, [%4];" \
        : "=r"(r0), "=r"(r1), "=r"(r2), "=r"(r3) : "r"(addr))
#define LDMX4T(r0, r1, r2, r3, addr)                                         \
    asm volatile("ldmatrix.sync.aligned.m8n8.x4.trans.shared.b16 {%0,%1,%2,%3}, [%4];" \
        : "=r"(r0), "=r"(r1), "=r"(r2), "=r"(r3) : "r"(addr))
#define MMA16816(c, a0, a1, a2, a3, b0, b1)                                  \
    asm volatile("mma.sync.aligned.m16n8k16.row.col.f32.bf16.bf16.f32 "      \
        "{%0,%1,%2,%3}, {%4,%5,%6,%7}, {%8,%9}, {%0,%1,%2,%3};"              \
        : "+f"((c)[0]), "+f"((c)[1]), "+f"((c)[2]), "+f"((c)[3])             \
        : "r"(a0), "r"(a1), "r"(a2), "r"(a3), "r"(b0), "r"(b1))
#define IMMA16832(c, a0_, a1_, a2_, a3_, b0_, b1_)                           \
    asm volatile("mma.sync.aligned.m16n8k32.row.col.s32.s8.s8.s32 "          \
        "{%0,%1,%2,%3}, {%4,%5,%6,%7}, {%8,%9}, {%0,%1,%2,%3};"              \
        : "+r"((c)[0]), "+r"((c)[1]), "+r"((c)[2]), "+r"((c)[3])             \
        : "r"(a0_), "r"(a1_), "r"(a2_), "r"(a3_), "r"(b0_), "r"(b1_))
#define PACKBF2(r, lo, hi)                                                   \
    asm("cvt.rn.bf16x2.f32 %0, %1, %2;" : "=r"(r) : "f"(hi), "f"(lo))
#define CP16(dst, src)                                                       \
    asm volatile("cp.async.cg.shared.global [%0], [%1], 16;" :: "r"(dst), "l"(src))
#define CP_COMMIT() asm volatile("cp.async.commit_group;" ::: "memory")
#define CP_WAIT(n)  asm volatile("cp.async.wait_group %0;" :: "n"(n) : "memory")

// ---------------- quantize rows of 1024 fp32 -> 2x int8 limbs + scale -----
// v ~= s*(a1*128 + a0),  s = rowmax/16383,  a1 in [-128,127], a0 in [-64,127]
__global__ __launch_bounds__(256) void quant_rows(
    const float* __restrict__ src, int8_t* __restrict__ q1,
    int8_t* __restrict__ q0, float* __restrict__ scale)
{
    const int row = blockIdx.x;
    const int tid = threadIdx.x;
    const float4 v = ((const float4*)(src + (size_t)row * 1024))[tid];
    float m = fmaxf(fmaxf(fabsf(v.x), fabsf(v.y)), fmaxf(fabsf(v.z), fabsf(v.w)));
    #pragma unroll
    for (int s = 16; s; s >>= 1) m = fmaxf(m, __shfl_xor_sync(0xffffffffu, m, s));
    __shared__ float red[8];
    if ((tid & 31) == 0) red[tid >> 5] = m;
    __syncthreads();
    float mm = red[0];
    #pragma unroll
    for (int i = 1; i < 8; i++) mm = fmaxf(mm, red[i]);

    const float inv = mm > 0.f ? 16383.0f / mm : 0.f;
    if (tid == 0) scale[row] = mm * (1.0f / 16383.0f);

    const float vv[4] = {v.x, v.y, v.z, v.w};
    char c1[4], c0[4];
    #pragma unroll
    for (int j = 0; j < 4; j++) {
        int q = (int)rintf(vv[j] * inv);
        q = max(-16383, min(16383, q));
        int a1 = min(127, (q + 64) >> 7);
        int a0 = q - (a1 << 7);
        c1[j] = (char)a1;
        c0[j] = (char)a0;
    }
    *(char4*)(q1 + (size_t)row * 1024 + tid * 4) = make_char4(c1[0], c1[1], c1[2], c1[3]);
    *(char4*)(q0 + (size_t)row * 1024 + tid * 4) = make_char4(c0[0], c0[1], c0[2], c0[3]);
}

// ---------------- int8 2-limb tensor-core GEMM (IMMA m16n8k32) ------------
// D[m,n] = sA[m]*sB[n]*(main*16384 + cross*128) + bias[n]
// main = A1*B1; cross = A1*B0 + A0*B1 (shared int32 accumulator; A0*B0 dropped).
// CTA 128x128, 512 threads = 16 warps (4m x 4n), warp tile 32x32, 4-stage cp.async.
// MODE 0: bf16 hi/lo split-scatter into g_{Q,K,V}{h,l}.  MODE 1: fp32 out.
template <int MODE>
__global__ __launch_bounds__(512, 1) void gemm_i8_kernel(
    const int8_t* __restrict__ Aq1, const int8_t* __restrict__ Aq0,
    const int8_t* __restrict__ Bq1, const int8_t* __restrict__ Bq0,
    const float* __restrict__ sA, const float* __restrict__ sB,
    const float* __restrict__ bias, float* __restrict__ Cout)
{
    extern __shared__ char smem[];
    const uint32_t sb = smem_u32(smem);
    const int tid = threadIdx.x;
    const int wid = tid >> 5;
    const int lane = tid & 31;
    const int warp_m = wid & 3;      // 4 x 32 rows
    const int warp_n = wid >> 2;     // 4 x 32 cols
    const int bn = blockIdx.x, bm = blockIdx.y;

    // cp.async: thread -> (tile, row); 2x 16B per row of 32B
    const int ct = tid >> 7;          // 0..3: A1, A0, B1, B0
    const int crow = tid & 127;
    const int8_t* const bases[4] = {
        Aq1 + (size_t)(bm * 128 + crow) * K_,
        Aq0 + (size_t)(bm * 128 + crow) * K_,
        Bq1 + (size_t)(bn * 128 + crow) * K_,
        Bq0 + (size_t)(bn * 128 + crow) * K_ };
    const int8_t* const csrc = bases[ct];
    const uint32_t cdst = sb + (uint32_t)(ct * ITILE_B + crow * ISP);

    // ldmatrix per-lane byte offsets within a tile
    const uint32_t aoff = (uint32_t)(
        (warp_m * 32 + (lane & 7) + ((lane >> 3) & 1) * 8) * ISP + (lane >> 4) * 16);
    const uint32_t boff = (uint32_t)(
        (warp_n * 32 + (lane & 7) + (lane >> 4) * 8) * ISP + ((lane >> 3) & 1) * 16);

    int accm[2][4][4], accc[2][4][4];
    #pragma unroll
    for (int i = 0; i < 2; i++)
        #pragma unroll
        for (int j = 0; j < 4; j++)
            #pragma unroll
            for (int c = 0; c < 4; c++) { accm[i][j][c] = 0; accc[i][j][c] = 0; }

    const int NT = K_ / 32;   // 32

    // prologue: stages 0..2
    #pragma unroll
    for (int st = 0; st < INSTAGE - 1; st++) {
        CP16(cdst + st * ISTAGE_B,      csrc + st * 32);
        CP16(cdst + st * ISTAGE_B + 16, csrc + st * 32 + 16);
        CP_COMMIT();
    }

    for (int it = 0; it < NT; ++it) {
        CP_WAIT(INSTAGE - 2);
        __syncthreads();
        const uint32_t tb = sb + (uint32_t)(it & (INSTAGE - 1)) * ISTAGE_B;

        if (it + INSTAGE - 1 < NT) {
            const uint32_t db = cdst + (uint32_t)((it + INSTAGE - 1) & (INSTAGE - 1)) * ISTAGE_B;
            CP16(db,      csrc + (it + INSTAGE - 1) * 32);
            CP16(db + 16, csrc + (it + INSTAGE - 1) * 32 + 16);
        }
        CP_COMMIT();

        uint32_t a1f[2][4], a0f[2][4];
        #pragma unroll
        for (int mf = 0; mf < 2; mf++) {
            const uint32_t ao = tb + aoff + (uint32_t)(mf * 16 * ISP);
            LDMX4(a1f[mf][0], a1f[mf][1], a1f[mf][2], a1f[mf][3], ao);
            LDMX4(a0f[mf][0], a0f[mf][1], a0f[mf][2], a0f[mf][3], ao + ITILE_B);
        }
        uint32_t b1f[2][4], b0f[2][4];
        #pragma unroll
        for (int ng = 0; ng < 2; ng++) {
            const uint32_t bo = tb + boff + (uint32_t)(ng * 16 * ISP);
            LDMX4(b1f[ng][0], b1f[ng][1], b1f[ng][2], b1f[ng][3], bo + 2 * ITILE_B);
            LDMX4(b0f[ng][0], b0f[ng][1], b0f[ng][2], b0f[ng][3], bo + 3 * ITILE_B);
        }
        #pragma unroll
        for (int mf = 0; mf < 2; mf++)
            #pragma unroll
            for (int nf = 0; nf < 4; nf++) {
                const int ng = nf >> 1, hh = (nf & 1) * 2;
                IMMA16832(accm[mf][nf], a1f[mf][0], a1f[mf][1], a1f[mf][2], a1f[mf][3],
                          b1f[ng][hh], b1f[ng][hh + 1]);
                IMMA16832(accc[mf][nf], a1f[mf][0], a1f[mf][1], a1f[mf][2], a1f[mf][3],
                          b0f[ng][hh], b0f[ng][hh + 1]);
                IMMA16832(accc[mf][nf], a0f[mf][0], a0f[mf][1], a0f[mf][2], a0f[mf][3],
                          b1f[ng][hh], b1f[ng][hh + 1]);
            }
    }
    CP_WAIT(0);

    // ---- direct-from-fragment epilogue ----
    const int g = lane >> 2, tg = lane & 3;
    #pragma unroll
    for (int mf = 0; mf < 2; mf++) {
        #pragma unroll
        for (int nf = 0; nf < 4; nf++) {
            const int gc = bn * 128 + warp_n * 32 + nf * 8 + tg * 2;   // global col
            const float sb0 = sB[gc], sb1 = sB[gc + 1];
            const float bb0 = bias[gc], bb1 = bias[gc + 1];
            const int r0 = bm * 128 + warp_m * 32 + mf * 16 + g;       // global row
            const float sa0 = sA[r0], sa1 = sA[r0 + 8];
            const float v0 = fmaf(__int2float_rn(accm[mf][nf][0]), 16384.f,
                                  __int2float_rn(accc[mf][nf][0]) * 128.f) * sa0 * sb0 + bb0;
            const float v1 = fmaf(__int2float_rn(accm[mf][nf][1]), 16384.f,
                                  __int2float_rn(accc[mf][nf][1]) * 128.f) * sa0 * sb1 + bb1;
            const float v2 = fmaf(__int2float_rn(accm[mf][nf][2]), 16384.f,
                                  __int2float_rn(accc[mf][nf][2]) * 128.f) * sa1 * sb0 + bb0;
            const float v3 = fmaf(__int2float_rn(accm[mf][nf][3]), 16384.f,
                                  __int2float_rn(accc[mf][nf][3]) * 128.f) * sa1 * sb1 + bb1;
            if (MODE == 0) {
                const int sel = gc >> 10;
                const int within = gc & 1023;
                const int h = within >> 6;
                const int dd = within & 63;
                __nv_bfloat16 *dh, *dl;
                if (sel == 0)      { dh = g_Qh; dl = g_Ql; }
                else if (sel == 1) { dh = g_Kh; dl = g_Kl; }
                else               { dh = g_Vh; dl = g_Vl; }
                #pragma unroll
                for (int rr = 0; rr < 2; rr++) {
                    const int m = r0 + rr * 8;
                    const int b = m >> 11, t = m & 2047;
                    const float y0 = rr ? v2 : v0, y1 = rr ? v3 : v1;
                    uint32_t hp, lp;
                    PACKBF2(hp, y0, y1);
                    const float e0 = y0 - __uint_as_float(hp << 16);
                    const float e1 = y1 - __uint_as_float(hp & 0xFFFF0000u);
                    PACKBF2(lp, e0, e1);
                    const size_t o = (((size_t)(b * H_ + h)) * T_ + t) * D_ + dd;
                    *(uint32_t*)(dh + o) = hp;
                    *(uint32_t*)(dl + o) = lp;
                }
            } else {
                #pragma unroll
                for (int rr = 0; rr < 2; rr++) {
                    const int m = r0 + rr * 8;
                    float2 y;
                    y.x = rr ? v2 : v0;
                    y.y = rr ? v3 : v1;
                    *(float2*)(Cout + (size_t)m * C_ + gc) = y;
                }
            }
        }
    }
}

// softcap+mask+exp with fixed max 30: p = exp(-60/(E+1)), E = exp(s/15)
__device__ __forceinline__ float softp(float raw, int qr, int kg, int P) {
    const float sc = raw * 0.125f;
    const float E = __expf(sc * (1.0f / 15.0f));
    const float p = __expf(__fdividef(-60.0f, E + 1.0f));
    const bool valid = ((kg <= qr) && (qr - kg <= WIN_)) || (kg < P);
    return valid ? p : 0.0f;
}

// ---------------------------------------------------------------------------
// HMMA attention: 128 q-rows/CTA, 8 warps (16 q-rows each), 64-key tiles.
// QK^T: Qh*Kh + Qh*Kl + Ql*Kh.  PV: Ph*Vh + Ph*Vl + Pl*Vh.
// Epilogue writes fp32 y (quantized afterward for the int8 proj GEMM).
// ---------------------------------------------------------------------------
__global__ __launch_bounds__(256, 2) void attn_kernel(const int* __restrict__ spl)
{
    extern __shared__ __nv_bfloat16 asmem[];
    __nv_bfloat16* Qh = asmem;               // [128][ASP]
    __nv_bfloat16* Ql = Qh + 128 * ASP;
    __nv_bfloat16* Kh = Ql + 128 * ASP;      // [64][ASP]
    __nv_bfloat16* Kl = Kh + 64 * ASP;
    __nv_bfloat16* Vh = Kl + 64 * ASP;       // [64][ASP]
    __nv_bfloat16* Vl = Vh + 64 * ASP;

    const int tid = threadIdx.x;
    const int wid = tid >> 5;      // 0..7
    const int lane = tid & 31;
    const int q0 = blockIdx.x * 128;
    const int h = blockIdx.y;
    const int b = blockIdx.z;
    const size_t bh = (size_t)(b * H_ + h) * T_;
    const int P = spl[b];

    for (int i = tid; i < 2048; i += 256) {
        const int arr = i >> 10;
        const int r = (i >> 3) & 127;
        const int c8 = i & 7;
        const __nv_bfloat16* src = (arr == 0 ? g_Qh : g_Ql) + (bh + q0 + r) * D_ + c8 * 8;
        __nv_bfloat16* dst = (arr == 0 ? Qh : Ql) + r * ASP + c8 * 8;
        *(uint4*)dst = *(const uint4*)src;
    }

    const int a_row = wid * 16 + (lane & 7) + ((lane >> 3) & 1) * 8;
    const int a_kg = (lane >> 4) * 8;
    const uint32_t qh_a = smem_u32(Qh + a_row * ASP + a_kg);
    const uint32_t ql_a = smem_u32(Ql + a_row * ASP + a_kg);
    const int k_row = (lane & 7) + (lane >> 4) * 8;
    const int k_col = ((lane >> 3) & 1) * 8;
    const uint32_t kh_a = smem_u32(Kh + k_row * ASP + k_col);
    const uint32_t kl_a = smem_u32(Kl + k_row * ASP + k_col);
    const int v_row = ((lane >> 3) & 1) * 8 + (lane & 7);
    const int v_col = (lane >> 4) * 8;
    const uint32_t vh_a = smem_u32(Vh + v_row * ASP + v_col);
    const uint32_t vl_a = smem_u32(Vl + v_row * ASP + v_col);

    float o[8][4];
    #pragma unroll
    for (int i = 0; i < 8; i++)
        #pragma unroll
        for (int j = 0; j < 4; j++) o[i][j] = 0.f;
    float lsum0 = 0.f, lsum1 = 0.f;
    const int row0 = q0 + wid * 16 + (lane >> 2);

    for (int kt = 0; kt < T_ / 64; kt++) {
        const int k0 = kt * 64;
        const bool tv = (k0 < P) || ((k0 <= q0 + 127) && (k0 + 63 >= q0 - WIN_));
        if (!tv) continue;

        __syncthreads();
        for (int i = tid; i < 2048; i += 256) {
            const int arr = i >> 9;
            const int r = (i >> 3) & 63;
            const int c8 = i & 7;
            const __nv_bfloat16* src =
                (arr == 0 ? g_Kh : arr == 1 ? g_Kl : arr == 2 ? g_Vh : g_Vl)
                + (bh + k0 + r) * D_ + c8 * 8;
            __nv_bfloat16* dst =
                (arr == 0 ? Kh : arr == 1 ? Kl : arr == 2 ? Vh : Vl) + r * ASP + c8 * 8;
            *(uint4*)dst = *(const uint4*)src;
        }
        __syncthreads();

        float s[8][4];
        #pragma unroll
        for (int i = 0; i < 8; i++)
            #pragma unroll
            for (int j = 0; j < 4; j++) s[i][j] = 0.f;

        #pragma unroll
        for (int kk4 = 0; kk4 < 4; kk4++) {
            uint32_t qa_h[4], qa_l[4];
            LDMX4(qa_h[0], qa_h[1], qa_h[2], qa_h[3], qh_a + kk4 * 32);
            LDMX4(qa_l[0], qa_l[1], qa_l[2], qa_l[3], ql_a + kk4 * 32);
            #pragma unroll
            for (int nf2 = 0; nf2 < 4; nf2++) {
                uint32_t kb_h[4], kb_l[4];
                const uint32_t off = (uint32_t)(nf2 * 16 * ASP) * 2 + kk4 * 32;
                LDMX4(kb_h[0], kb_h[1], kb_h[2], kb_h[3], kh_a + off);
                LDMX4(kb_l[0], kb_l[1], kb_l[2], kb_l[3], kl_a + off);
                MMA16816(s[nf2*2], qa_h[0], qa_h[1], qa_h[2], qa_h[3], kb_h[0], kb_h[1]);
                MMA16816(s[nf2*2], qa_h[0], qa_h[1], qa_h[2], qa_h[3], kb_l[0], kb_l[1]);
                MMA16816(s[nf2*2], qa_l[0], qa_l[1], qa_l[2], qa_l[3], kb_h[0], kb_h[1]);
                MMA16816(s[nf2*2+1], qa_h[0], qa_h[1], qa_h[2], qa_h[3], kb_h[2], kb_h[3]);
                MMA16816(s[nf2*2+1], qa_h[0], qa_h[1], qa_h[2], qa_h[3], kb_l[2], kb_l[3]);
                MMA16816(s[nf2*2+1], qa_l[0], qa_l[1], qa_l[2], qa_l[3], kb_h[2], kb_h[3]);
            }
        }

        #pragma unroll
        for (int kc = 0; kc < 4; kc++) {
            uint32_t pah[4], pal[4];
            #pragma unroll
            for (int j = 0; j < 2; j++) {
                const int nf = kc * 2 + j;
                const int cb = k0 + nf * 8 + (lane & 3) * 2;
                const float p0 = softp(s[nf][0], row0,     cb,     P);
                const float p1 = softp(s[nf][1], row0,     cb + 1, P);
                const float p2 = softp(s[nf][2], row0 + 8, cb,     P);
                const float p3 = softp(s[nf][3], row0 + 8, cb + 1, P);
                lsum0 += p0 + p1;
                lsum1 += p2 + p3;
                uint32_t h01, h23;
                PACKBF2(h01, p0, p1);
                PACKBF2(h23, p2, p3);
                pah[j*2]   = h01;
                pah[j*2+1] = h23;
                const float r0 = p0 - __uint_as_float(h01 << 16);
                const float r1 = p1 - __uint_as_float(h01 & 0xFFFF0000u);
                const float r2 = p2 - __uint_as_float(h23 << 16);
                const float r3 = p3 - __uint_as_float(h23 & 0xFFFF0000u);
                uint32_t l01, l23;
                PACKBF2(l01, r0, r1);
                PACKBF2(l23, r2, r3);
                pal[j*2]   = l01;
                pal[j*2+1] = l23;
            }
            #pragma unroll
            for (int nf2 = 0; nf2 < 4; nf2++) {
                uint32_t vb_h[4], vb_l[4];
                const uint32_t off = (uint32_t)(kc * 16 * ASP + nf2 * 16) * 2;
                LDMX4T(vb_h[0], vb_h[1], vb_h[2], vb_h[3], vh_a + off);
                LDMX4T(vb_l[0], vb_l[1], vb_l[2], vb_l[3], vl_a + off);
                MMA16816(o[nf2*2], pah[0], pah[1], pah[2], pah[3], vb_h[0], vb_h[1]);
                MMA16816(o[nf2*2], pah[0], pah[1], pah[2], pah[3], vb_l[0], vb_l[1]);
                MMA16816(o[nf2*2], pal[0], pal[1], pal[2], pal[3], vb_h[0], vb_h[1]);
                MMA16816(o[nf2*2+1], pah[0], pah[1], pah[2], pah[3], vb_h[2], vb_h[3]);
                MMA16816(o[nf2*2+1], pah[0], pah[1], pah[2], pah[3], vb_l[2], vb_l[3]);
                MMA16816(o[nf2*2+1], pal[0], pal[1], pal[2], pal[3], vb_h[2], vb_h[3]);
            }
        }
    }

    lsum0 += __shfl_xor_sync(0xffffffffu, lsum0, 1);
    lsum0 += __shfl_xor_sync(0xffffffffu, lsum0, 2);
    lsum1 += __shfl_xor_sync(0xffffffffu, lsum1, 1);
    lsum1 += __shfl_xor_sync(0xffffffffu, lsum1, 2);
    const float inv0 = 1.0f / lsum0;
    const float inv1 = 1.0f / lsum1;

    float* yp0 = g_y + ((size_t)(b * T_) + row0) * C_ + h * D_ + (lane & 3) * 2;
    float* yp1 = yp0 + (size_t)8 * C_;
    #pragma unroll
    for (int nf = 0; nf < 8; nf++) {
        float2 y0, y1;
        y0.x = o[nf][0] * inv0; y0.y = o[nf][1] * inv0;
        y1.x = o[nf][2] * inv1; y1.y = o[nf][3] * inv1;
        *(float2*)(yp0 + nf * 8) = y0;
        *(float2*)(yp1 + nf * 8) = y1;
    }
}

// ---------------------------------------------------------------------------
extern "C" void kernel_launch(void* const* d_in, const int* in_sizes, int n_in,
                              void* d_out, int out_size)
{
    (void)in_sizes; (void)n_in; (void)out_size;
    const float* x    = (const float*)d_in[0];
    const int*   spl  = (const int*)  d_in[1];
    const float* Wqkv = (const float*)d_in[2];
    const float* bqkv = (const float*)d_in[3];
    const float* Wprj = (const float*)d_in[4];
    const float* bprj = (const float*)d_in[5];
    float* out = (float*)d_out;

    cudaFuncSetAttribute(attn_kernel,
                         cudaFuncAttributeMaxDynamicSharedMemorySize, ATTN_SMEM);
    cudaFuncSetAttribute(gemm_i8_kernel<0>,
                         cudaFuncAttributeMaxDynamicSharedMemorySize, IGSMEM);
    cudaFuncSetAttribute(gemm_i8_kernel<1>,
                         cudaFuncAttributeMaxDynamicSharedMemorySize, IGSMEM);

    int8_t *xq1, *xq0, *wq1, *wq0, *wp1, *wp0, *yq1, *yq0;
    float *sx, *swq, *swp, *sy, *yf;
    cudaGetSymbolAddress((void**)&xq1, g_xq1); cudaGetSymbolAddress((void**)&xq0, g_xq0);
    cudaGetSymbolAddress((void**)&wq1, g_wq1); cudaGetSymbolAddress((void**)&wq0, g_wq0);
    cudaGetSymbolAddress((void**)&wp1, g_wp1); cudaGetSymbolAddress((void**)&wp0, g_wp0);
    cudaGetSymbolAddress((void**)&yq1, g_yq1); cudaGetSymbolAddress((void**)&yq0, g_yq0);
    cudaGetSymbolAddress((void**)&sx,  g_sx);  cudaGetSymbolAddress((void**)&swq, g_swq);
    cudaGetSymbolAddress((void**)&swp, g_swp); cudaGetSymbolAddress((void**)&sy,  g_sy);
    cudaGetSymbolAddress((void**)&yf,  g_y);

    // 0) quantize x, Wqkv, Wproj into int8 limbs + per-row scales
    quant_rows<<<B_*T_, 256>>>(x, xq1, xq0, sx);
    quant_rows<<<3*C_, 256>>>(Wqkv, wq1, wq0, swq);
    quant_rows<<<C_, 256>>>(Wprj, wp1, wp0, swp);

    // 1) QKV projection (IMMA int8) -> g_{Q,K,V}{h,l}
    gemm_i8_kernel<0><<<dim3(3*C_/128, B_*T_/128), 512, IGSMEM>>>(
        xq1, xq0, wq1, wq0, sx, swq, bqkv, nullptr);

    // 2) attention (HMMA bf16) -> g_y (fp32)
    attn_kernel<<<dim3(T_/128, H_, B_), 256, ATTN_SMEM>>>(spl);

    // 3) quantize y, then output projection (IMMA int8) -> d_out
    quant_rows<<<B_*T_, 256>>>(yf, yq1, yq0, sy);
    gemm_i8_kernel<1><<<dim3(C_/128, B_*T_/128), 512, IGSMEM>>>(
        yq1, yq0, wp1, wp0, sy, swp, bprj, out);
}

// round 9
// speedup vs baseline: 3.3881x; 3.3881x over previous
#include <cuda_runtime.h>
#include <cuda_bf16.h>
#include <cuda_fp16.h>
#include <math.h>
#include <stdint.h>

// Problem constants
#define B_ 2
#define T_ 2048
#define C_ 1024
#define H_ 16
#define D_ 64
#define WIN_ 512
#define K_ 1024

// GEMM tiling: fp16 single-product, BK=16, 4-stage cp.async
#define SP 24                       // padded row stride (fp16 elems) = 48 B
#define TILE_B (128 * SP * 2)       // 6144 B per 128x16 tile
#define STAGE_B (2 * TILE_B)        // A, B = 12288 B
#define NSTAGE 4
#define GSMEM (NSTAGE * STAGE_B)    // 49152 B

// Attention smem (static): Qf[128]+Kf[64] fp16, Vh/Vl[64] bf16, stride ASP
#define ASP 72

// ---------------- scratch (allocation-free) ----------------
__device__ __half        g_Qf[B_*H_*T_*D_];
__device__ __half        g_Kf[B_*H_*T_*D_];
__device__ __nv_bfloat16 g_Vh[B_*H_*T_*D_], g_Vl[B_*H_*T_*D_];
__device__ __half        g_xf[B_*T_*C_];
__device__ __half        g_wqf[3*C_*C_];
__device__ __half        g_wpf[C_*C_];
__device__ __half        g_yf[B_*T_*C_];

__device__ __forceinline__ uint32_t smem_u32(const void* p) {
    uint32_t a;
    asm("{ .reg .u64 t; cvta.to.shared.u64 t, %1; cvt.u32.u64 %0, t; }"
        : "=r"(a) : "l"(p));
    return a;
}
#define LDMX4(r0, r1, r2, r3, addr)                                          \
    asm volatile("ldmatrix.sync.aligned.m8n8.x4.shared.b16 {%0,%1,%2,%3}, [%4];" \
        : "=r"(r0), "=r"(r1), "=r"(r2), "=r"(r3) : "r"(addr))
#define LDMX4T(r0, r1, r2, r3, addr)                                         \
    asm volatile("ldmatrix.sync.aligned.m8n8.x4.trans.shared.b16 {%0,%1,%2,%3}, [%4];" \
        : "=r"(r0), "=r"(r1), "=r"(r2), "=r"(r3) : "r"(addr))
// bf16 HMMA
#define MMA16816(c, a0, a1, a2, a3, b0, b1)                                  \
    asm volatile("mma.sync.aligned.m16n8k16.row.col.f32.bf16.bf16.f32 "      \
        "{%0,%1,%2,%3}, {%4,%5,%6,%7}, {%8,%9}, {%0,%1,%2,%3};"              \
        : "+f"((c)[0]), "+f"((c)[1]), "+f"((c)[2]), "+f"((c)[3])             \
        : "r"(a0), "r"(a1), "r"(a2), "r"(a3), "r"(b0), "r"(b1))
// fp16 HMMA
#define MMAH16816(c, a0, a1, a2, a3, b0, b1)                                 \
    asm volatile("mma.sync.aligned.m16n8k16.row.col.f32.f16.f16.f32 "        \
        "{%0,%1,%2,%3}, {%4,%5,%6,%7}, {%8,%9}, {%0,%1,%2,%3};"              \
        : "+f"((c)[0]), "+f"((c)[1]), "+f"((c)[2]), "+f"((c)[3])             \
        : "r"(a0), "r"(a1), "r"(a2), "r"(a3), "r"(b0), "r"(b1))
#define PACKBF2(r, lo, hi)                                                   \
    asm("cvt.rn.bf16x2.f32 %0, %1, %2;" : "=r"(r) : "f"(hi), "f"(lo))
#define CP16(dst, src)                                                       \
    asm volatile("cp.async.cg.shared.global [%0], [%1], 16;" :: "r"(dst), "l"(src))
#define CP_COMMIT() asm volatile("cp.async.commit_group;" ::: "memory")
#define CP_WAIT(n)  asm volatile("cp.async.wait_group %0;" :: "n"(n) : "memory")

// ---------------- convert fp32 -> fp16 ----------------
__global__ __launch_bounds__(256) void cvt_f16(
    const float* __restrict__ s, __half* __restrict__ d, int n4)
{
    int i = blockIdx.x * 256 + threadIdx.x;
    if (i >= n4) return;
    float4 v = ((const float4*)s)[i];
    __half2 h0 = __halves2half2(__float2half_rn(v.x), __float2half_rn(v.y));
    __half2 h1 = __halves2half2(__float2half_rn(v.z), __float2half_rn(v.w));
    ((__half2*)d)[2*i]   = h0;
    ((__half2*)d)[2*i+1] = h1;
}

// ---------------- fp16 single-product tensor-core GEMM --------------------
// D[m,n] = sum_k A[m,k]*W[n,k] + bias[n]  (single fp16 HMMA product)
// CTA 128x128, BK=16, 256 threads = 8 warps (4m x 2n), warp tile 32x64,
// 4-stage cp.async, ONE __syncthreads per K16, direct-from-fragment epilogue.
// MODE 0: q,k -> fp16; v -> bf16 hi/lo (scatter [B,H,T,d]).  MODE 1: fp32 out.
template <int MODE>
__global__ __launch_bounds__(256, 2) void gemm_f16_kernel(
    const __half* __restrict__ Af, const __half* __restrict__ Bf,
    const float* __restrict__ bias, float* __restrict__ Cout)
{
    extern __shared__ char smem[];
    const uint32_t sb = smem_u32(smem);
    const int tid = threadIdx.x;
    const int wid = tid >> 5;
    const int lane = tid & 31;
    const int warp_m = wid & 3;      // 4 x 32 rows
    const int warp_n = wid >> 2;     // 2 x 64 cols
    const int bn = blockIdx.x, bm = blockIdx.y;

    // cp.async: thread -> (tile ct, row); 2x 16B chunks per 32B row
    const int ct = tid >> 7;          // 0=A, 1=B
    const int crow = tid & 127;
    const __half* const csrc = (ct == 0)
        ? Af + (size_t)(bm * 128 + crow) * K_
        : Bf + (size_t)(bn * 128 + crow) * K_;
    const uint32_t cdst = sb + (uint32_t)(ct * TILE_B + crow * SP * 2);

    // ldmatrix per-lane byte offsets within a tile
    const uint32_t aoff = (uint32_t)(
        (warp_m * 32 + (lane & 7) + ((lane >> 3) & 1) * 8) * SP
        + (lane >> 4) * 8) * 2;
    const uint32_t boff = (uint32_t)(
        (warp_n * 64 + (lane & 7) + (lane >> 4) * 8) * SP
        + ((lane >> 3) & 1) * 8) * 2;

    float acc[2][8][4];
    #pragma unroll
    for (int i = 0; i < 2; i++)
        #pragma unroll
        for (int j = 0; j < 8; j++)
            #pragma unroll
            for (int c = 0; c < 4; c++) acc[i][j][c] = 0.f;

    const int NT = K_ / 16;   // 64

    #pragma unroll
    for (int st = 0; st < NSTAGE - 1; st++) {
        CP16(cdst + st * STAGE_B,      csrc + st * 16);
        CP16(cdst + st * STAGE_B + 16, csrc + st * 16 + 8);
        CP_COMMIT();
    }

    for (int it = 0; it < NT; ++it) {
        CP_WAIT(NSTAGE - 2);
        __syncthreads();
        const uint32_t tb = sb + (uint32_t)(it & (NSTAGE - 1)) * STAGE_B;

        if (it + NSTAGE - 1 < NT) {
            const uint32_t db = cdst + (uint32_t)((it + NSTAGE - 1) & (NSTAGE - 1)) * STAGE_B;
            CP16(db,      csrc + (it + NSTAGE - 1) * 16);
            CP16(db + 16, csrc + (it + NSTAGE - 1) * 16 + 8);
        }
        CP_COMMIT();

        uint32_t af[2][4];
        #pragma unroll
        for (int mf = 0; mf < 2; mf++) {
            const uint32_t ao = tb + aoff + (uint32_t)(mf * 16 * SP) * 2;
            LDMX4(af[mf][0], af[mf][1], af[mf][2], af[mf][3], ao);
        }
        #pragma unroll
        for (int nf2 = 0; nf2 < 4; nf2++) {
            uint32_t bf[4];
            const uint32_t bo = tb + TILE_B + boff + (uint32_t)(nf2 * 16 * SP) * 2;
            LDMX4(bf[0], bf[1], bf[2], bf[3], bo);
            #pragma unroll
            for (int mf = 0; mf < 2; mf++) {
                MMAH16816(acc[mf][nf2*2],   af[mf][0], af[mf][1], af[mf][2], af[mf][3],
                          bf[0], bf[1]);
                MMAH16816(acc[mf][nf2*2+1], af[mf][0], af[mf][1], af[mf][2], af[mf][3],
                          bf[2], bf[3]);
            }
        }
    }
    CP_WAIT(0);

    // ---- direct-from-fragment epilogue ----
    const int g = lane >> 2, tg = lane & 3;
    #pragma unroll
    for (int mf = 0; mf < 2; mf++) {
        #pragma unroll
        for (int nf = 0; nf < 8; nf++) {
            const int gc = bn * 128 + warp_n * 64 + nf * 8 + tg * 2;
            const float b0 = bias[gc], b1 = bias[gc + 1];
            const int r0 = bm * 128 + warp_m * 32 + mf * 16 + g;
            const float v0 = acc[mf][nf][0] + b0, v1 = acc[mf][nf][1] + b1;
            const float v2 = acc[mf][nf][2] + b0, v3 = acc[mf][nf][3] + b1;
            if (MODE == 0) {
                const int sel = gc >> 10;
                const int within = gc & 1023;
                const int h = within >> 6;
                const int dd = within & 63;
                #pragma unroll
                for (int rr = 0; rr < 2; rr++) {
                    const int m = r0 + rr * 8;
                    const int b = m >> 11, t = m & 2047;
                    const float y0 = rr ? v2 : v0, y1 = rr ? v3 : v1;
                    const size_t o = (((size_t)(b * H_ + h)) * T_ + t) * D_ + dd;
                    if (sel == 2) {
                        uint32_t hp, lp;
                        PACKBF2(hp, y0, y1);
                        const float e0 = y0 - __uint_as_float(hp << 16);
                        const float e1 = y1 - __uint_as_float(hp & 0xFFFF0000u);
                        PACKBF2(lp, e0, e1);
                        *(uint32_t*)(g_Vh + o) = hp;
                        *(uint32_t*)(g_Vl + o) = lp;
                    } else {
                        __half2 hv = __halves2half2(__float2half_rn(y0),
                                                    __float2half_rn(y1));
                        *(__half2*)((sel == 0 ? g_Qf : g_Kf) + o) = hv;
                    }
                }
            } else {
                #pragma unroll
                for (int rr = 0; rr < 2; rr++) {
                    const int m = r0 + rr * 8;
                    float2 y;
                    y.x = rr ? v2 : v0;
                    y.y = rr ? v3 : v1;
                    *(float2*)(Cout + (size_t)m * C_ + gc) = y;
                }
            }
        }
    }
}

// softcap+mask+exp with fixed max 30: p = exp(-60/(E+1)), E = exp(s/15)
__device__ __forceinline__ float softp(float raw, int qr, int kg, int P) {
    const float sc = raw * 0.125f;
    const float E = __expf(sc * (1.0f / 15.0f));
    const float p = __expf(__fdividef(-60.0f, E + 1.0f));
    const bool valid = ((kg <= qr) && (qr - kg <= WIN_)) || (kg < P);
    return valid ? p : 0.0f;
}

// ---------------------------------------------------------------------------
// Attention: 128 q-rows/CTA, 8 warps, 64-key tiles.
// QK^T: single fp16 product.  PV: Ph*Vh + Ph*Vl + Pl*Vh (bf16 hi/lo; P spans
// 26 decades under the fixed-max trick so fp16 would underflow).
// Epilogue writes y directly as fp16 (proj GEMM input).
// ---------------------------------------------------------------------------
__global__ __launch_bounds__(256, 2) void attn_kernel(const int* __restrict__ spl)
{
    __shared__ __half        Qf[128 * ASP];
    __shared__ __half        Kf[64 * ASP];
    __shared__ __nv_bfloat16 Vh[64 * ASP];
    __shared__ __nv_bfloat16 Vl[64 * ASP];

    const int tid = threadIdx.x;
    const int wid = tid >> 5;      // 0..7
    const int lane = tid & 31;
    const int q0 = blockIdx.x * 128;
    const int h = blockIdx.y;
    const int b = blockIdx.z;
    const size_t bh = (size_t)(b * H_ + h) * T_;
    const int P = spl[b];

    // load Q: 128 rows x 8 uint4
    for (int i = tid; i < 1024; i += 256) {
        const int r = i >> 3;
        const int c8 = i & 7;
        *(uint4*)(Qf + r * ASP + c8 * 8) =
            *(const uint4*)(g_Qf + (bh + q0 + r) * D_ + c8 * 8);
    }

    const int a_row = wid * 16 + (lane & 7) + ((lane >> 3) & 1) * 8;
    const int a_kg = (lane >> 4) * 8;
    const uint32_t qf_a = smem_u32(Qf + a_row * ASP + a_kg);
    const int k_row = (lane & 7) + (lane >> 4) * 8;
    const int k_col = ((lane >> 3) & 1) * 8;
    const uint32_t kf_a = smem_u32(Kf + k_row * ASP + k_col);
    const int v_row = ((lane >> 3) & 1) * 8 + (lane & 7);
    const int v_col = (lane >> 4) * 8;
    const uint32_t vh_a = smem_u32(Vh + v_row * ASP + v_col);
    const uint32_t vl_a = smem_u32(Vl + v_row * ASP + v_col);

    float o[8][4];
    #pragma unroll
    for (int i = 0; i < 8; i++)
        #pragma unroll
        for (int j = 0; j < 4; j++) o[i][j] = 0.f;
    float lsum0 = 0.f, lsum1 = 0.f;
    const int row0 = q0 + wid * 16 + (lane >> 2);

    for (int kt = 0; kt < T_ / 64; kt++) {
        const int k0 = kt * 64;
        const bool tv = (k0 < P) || ((k0 <= q0 + 127) && (k0 + 63 >= q0 - WIN_));
        if (!tv) continue;   // uniform across block

        __syncthreads();
        // K fp16 + V hi/lo bf16: 3 arrays x 64 rows x 8 uint4 = 1536
        for (int i = tid; i < 1536; i += 256) {
            const int arr = i >> 9;
            const int r = (i >> 3) & 63;
            const int c8 = i & 7;
            const size_t src_o = (bh + k0 + r) * D_ + c8 * 8;
            if (arr == 0)
                *(uint4*)(Kf + r * ASP + c8 * 8) = *(const uint4*)(g_Kf + src_o);
            else if (arr == 1)
                *(uint4*)(Vh + r * ASP + c8 * 8) = *(const uint4*)(g_Vh + src_o);
            else
                *(uint4*)(Vl + r * ASP + c8 * 8) = *(const uint4*)(g_Vl + src_o);
        }
        __syncthreads();

        // ---- QK^T (single fp16 product) -> s[8][4] ----
        float s[8][4];
        #pragma unroll
        for (int i = 0; i < 8; i++)
            #pragma unroll
            for (int j = 0; j < 4; j++) s[i][j] = 0.f;

        #pragma unroll
        for (int kk4 = 0; kk4 < 4; kk4++) {
            uint32_t qa[4];
            LDMX4(qa[0], qa[1], qa[2], qa[3], qf_a + kk4 * 32);
            #pragma unroll
            for (int nf2 = 0; nf2 < 4; nf2++) {
                uint32_t kb[4];
                LDMX4(kb[0], kb[1], kb[2], kb[3],
                      kf_a + (uint32_t)(nf2 * 16 * ASP) * 2 + kk4 * 32);
                MMAH16816(s[nf2*2],   qa[0], qa[1], qa[2], qa[3], kb[0], kb[1]);
                MMAH16816(s[nf2*2+1], qa[0], qa[1], qa[2], qa[3], kb[2], kb[3]);
            }
        }

        // ---- softcap/mask/exp + C->A repack + PV (bf16 3-product) ----
        #pragma unroll
        for (int kc = 0; kc < 4; kc++) {
            uint32_t pah[4], pal[4];
            #pragma unroll
            for (int j = 0; j < 2; j++) {
                const int nf = kc * 2 + j;
                const int cb = k0 + nf * 8 + (lane & 3) * 2;
                const float p0 = softp(s[nf][0], row0,     cb,     P);
                const float p1 = softp(s[nf][1], row0,     cb + 1, P);
                const float p2 = softp(s[nf][2], row0 + 8, cb,     P);
                const float p3 = softp(s[nf][3], row0 + 8, cb + 1, P);
                lsum0 += p0 + p1;
                lsum1 += p2 + p3;
                uint32_t h01, h23;
                PACKBF2(h01, p0, p1);
                PACKBF2(h23, p2, p3);
                pah[j*2]   = h01;
                pah[j*2+1] = h23;
                const float r0 = p0 - __uint_as_float(h01 << 16);
                const float r1 = p1 - __uint_as_float(h01 & 0xFFFF0000u);
                const float r2 = p2 - __uint_as_float(h23 << 16);
                const float r3 = p3 - __uint_as_float(h23 & 0xFFFF0000u);
                uint32_t l01, l23;
                PACKBF2(l01, r0, r1);
                PACKBF2(l23, r2, r3);
                pal[j*2]   = l01;
                pal[j*2+1] = l23;
            }
            #pragma unroll
            for (int nf2 = 0; nf2 < 4; nf2++) {
                uint32_t vb_h[4], vb_l[4];
                const uint32_t off = (uint32_t)(kc * 16 * ASP + nf2 * 16) * 2;
                LDMX4T(vb_h[0], vb_h[1], vb_h[2], vb_h[3], vh_a + off);
                LDMX4T(vb_l[0], vb_l[1], vb_l[2], vb_l[3], vl_a + off);
                MMA16816(o[nf2*2], pah[0], pah[1], pah[2], pah[3], vb_h[0], vb_h[1]);
                MMA16816(o[nf2*2], pah[0], pah[1], pah[2], pah[3], vb_l[0], vb_l[1]);
                MMA16816(o[nf2*2], pal[0], pal[1], pal[2], pal[3], vb_h[0], vb_h[1]);
                MMA16816(o[nf2*2+1], pah[0], pah[1], pah[2], pah[3], vb_h[2], vb_h[3]);
                MMA16816(o[nf2*2+1], pah[0], pah[1], pah[2], pah[3], vb_l[2], vb_l[3]);
                MMA16816(o[nf2*2+1], pal[0], pal[1], pal[2], pal[3], vb_h[2], vb_h[3]);
            }
        }
    }

    lsum0 += __shfl_xor_sync(0xffffffffu, lsum0, 1);
    lsum0 += __shfl_xor_sync(0xffffffffu, lsum0, 2);
    lsum1 += __shfl_xor_sync(0xffffffffu, lsum1, 1);
    lsum1 += __shfl_xor_sync(0xffffffffu, lsum1, 2);
    const float inv0 = 1.0f / lsum0;
    const float inv1 = 1.0f / lsum1;

    __half* yp0 = g_yf + ((size_t)(b * T_) + row0) * C_ + h * D_ + (lane & 3) * 2;
    __half* yp1 = yp0 + (size_t)8 * C_;
    #pragma unroll
    for (int nf = 0; nf < 8; nf++) {
        *(__half2*)(yp0 + nf * 8) = __halves2half2(
            __float2half_rn(o[nf][0] * inv0), __float2half_rn(o[nf][1] * inv0));
        *(__half2*)(yp1 + nf * 8) = __halves2half2(
            __float2half_rn(o[nf][2] * inv1), __float2half_rn(o[nf][3] * inv1));
    }
}

// ---------------------------------------------------------------------------
extern "C" void kernel_launch(void* const* d_in, const int* in_sizes, int n_in,
                              void* d_out, int out_size)
{
    (void)in_sizes; (void)n_in; (void)out_size;
    const float* x    = (const float*)d_in[0];
    const int*   spl  = (const int*)  d_in[1];
    const float* Wqkv = (const float*)d_in[2];
    const float* bqkv = (const float*)d_in[3];
    const float* Wprj = (const float*)d_in[4];
    const float* bprj = (const float*)d_in[5];
    float* out = (float*)d_out;

    cudaFuncSetAttribute(gemm_f16_kernel<0>,
                         cudaFuncAttributeMaxDynamicSharedMemorySize, GSMEM);
    cudaFuncSetAttribute(gemm_f16_kernel<1>,
                         cudaFuncAttributeMaxDynamicSharedMemorySize, GSMEM);

    __half *xf, *wqf, *wpf, *yf;
    cudaGetSymbolAddress((void**)&xf,  g_xf);
    cudaGetSymbolAddress((void**)&wqf, g_wqf);
    cudaGetSymbolAddress((void**)&wpf, g_wpf);
    cudaGetSymbolAddress((void**)&yf,  g_yf);

    // 0) convert inputs to fp16
    cvt_f16<<<(B_*T_*C_/4 + 255)/256, 256>>>(x, xf, B_*T_*C_/4);
    cvt_f16<<<(3*C_*C_/4 + 255)/256, 256>>>(Wqkv, wqf, 3*C_*C_/4);
    cvt_f16<<<(C_*C_/4 + 255)/256, 256>>>(Wprj, wpf, C_*C_/4);

    // 1) QKV projection (fp16 HMMA) -> g_Qf/g_Kf fp16, g_Vh/g_Vl bf16
    gemm_f16_kernel<0><<<dim3(3*C_/128, B_*T_/128), 256, GSMEM>>>(
        xf, wqf, bqkv, nullptr);

    // 2) attention -> g_yf fp16
    attn_kernel<<<dim3(T_/128, H_, B_), 256>>>(spl);

    // 3) output projection (fp16 HMMA) -> d_out
    gemm_f16_kernel<1><<<dim3(C_/128, B_*T_/128), 256, GSMEM>>>(
        yf, wpf, bprj, out);
}